// round 5
// baseline (speedup 1.0000x reference)
#include <cuda_runtime.h>
#include <cuda_bf16.h>
#include <math.h>
#include <stdint.h>

// ---------------------------------------------------------------------------
// Problem constants
// ---------------------------------------------------------------------------
#define QL 2048
#define BSZ 2
#define DM 1024
#define NH 16
#define DH 64
#define DI 4096
#define NTOK (QL*BSZ)          // 4096 rows, row t = i*BSZ + b

// ---------------------------------------------------------------------------
// Scratch (device globals; no allocation allowed)
// ---------------------------------------------------------------------------
__device__ float g_heads[NTOK * 3 * DM];   // qkv projections  [4096, 3072]
__device__ float g_rk[QL * DM];            // r @ r_net_w      [2048, 1024]
__device__ float g_attnvec[NTOK * DM];     // attention output [4096, 1024]
__device__ float g_attnout[NTOK * DM];     // o-proj output
__device__ float g_x[NTOK * DM];           // after LN1
__device__ float g_h[NTOK * DI];           // ffn hidden       [4096, 4096]
__device__ float g_core[NTOK * DM];        // ffn output

// ---------------------------------------------------------------------------
// tf32 helpers
// ---------------------------------------------------------------------------
__device__ __forceinline__ float to_tf32(float v) {
    uint32_t u;
    asm("cvt.rna.tf32.f32 %0, %1;" : "=r"(u) : "f"(v));
    return __uint_as_float(u);
}

#define MMA_TF32(d, a, b)                                                      \
    asm volatile(                                                              \
        "mma.sync.aligned.m16n8k8.row.col.f32.tf32.tf32.f32 "                  \
        "{%0,%1,%2,%3},{%4,%5,%6,%7},{%8,%9},{%0,%1,%2,%3};\n"                 \
        : "+f"(d[0]), "+f"(d[1]), "+f"(d[2]), "+f"(d[3])                       \
        : "r"(a[0]), "r"(a[1]), "r"(a[2]), "r"(a[3]), "r"(b[0]), "r"(b[1]))

// ---------------------------------------------------------------------------
// Generic tf32 GEMM: C[M,N] = A[M,K] @ B[K,N]  (+bias)(+relu per EPI)
// Tile 128x128x32, 256 threads (8 warps: 2 (m) x 4 (n), warp tile 64x32).
// EPI: 0 = plain store, 1 = bias + relu
// ---------------------------------------------------------------------------
template <int EPI>
__global__ void __launch_bounds__(256)
gemm_tf32(const float* __restrict__ A, const float* __restrict__ B,
          float* __restrict__ C, const float* __restrict__ bias,
          int M, int N, int K)
{
    const int bm = blockIdx.y * 128;
    const int bn = blockIdx.x * 128;

    __shared__ float As[128 * 36];   // stride 36 (pad)
    __shared__ float Bs[32 * 136];   // stride 136 (pad -> conflict-free frags)

    const int tid = threadIdx.x;
    const int w   = tid >> 5;
    const int l   = tid & 31;
    const int g   = l >> 2;   // group id 0..7
    const int t   = l & 3;    // thread-in-group 0..3
    const int wm  = (w & 1) * 64;
    const int wn  = (w >> 1) * 32;

    float c[4][4][4];
    #pragma unroll
    for (int mt = 0; mt < 4; mt++)
        #pragma unroll
        for (int nt = 0; nt < 4; nt++)
            #pragma unroll
            for (int q = 0; q < 4; q++) c[mt][nt][q] = 0.f;

    float4 ra[4], rb[4];

    const int KT = K / 32;

    #define LOAD_G(kt)                                                         \
        {                                                                      \
            const float* Ap = A + (long)bm * K + (kt) * 32;                    \
            _Pragma("unroll")                                                  \
            for (int it = 0; it < 4; it++) {                                   \
                int f = tid + it * 256;                                        \
                int rr = f >> 3, c4 = f & 7;                                   \
                ra[it] = *(const float4*)(Ap + (long)rr * K + c4 * 4);         \
            }                                                                  \
            const float* Bp = B + (long)(kt) * 32 * N + bn;                    \
            _Pragma("unroll")                                                  \
            for (int it = 0; it < 4; it++) {                                   \
                int f = tid + it * 256;                                        \
                int rr = f >> 5, c4 = f & 31;                                  \
                rb[it] = *(const float4*)(Bp + (long)rr * N + c4 * 4);         \
            }                                                                  \
        }

    #define STORE_S()                                                          \
        {                                                                      \
            _Pragma("unroll")                                                  \
            for (int it = 0; it < 4; it++) {                                   \
                int f = tid + it * 256;                                        \
                int rr = f >> 3, c4 = f & 7;                                   \
                float* p = As + rr * 36 + c4 * 4;                              \
                p[0] = to_tf32(ra[it].x); p[1] = to_tf32(ra[it].y);            \
                p[2] = to_tf32(ra[it].z); p[3] = to_tf32(ra[it].w);            \
            }                                                                  \
            _Pragma("unroll")                                                  \
            for (int it = 0; it < 4; it++) {                                   \
                int f = tid + it * 256;                                        \
                int rr = f >> 5, c4 = f & 31;                                  \
                float* p = Bs + rr * 136 + c4 * 4;                             \
                p[0] = to_tf32(rb[it].x); p[1] = to_tf32(rb[it].y);            \
                p[2] = to_tf32(rb[it].z); p[3] = to_tf32(rb[it].w);            \
            }                                                                  \
        }

    LOAD_G(0);
    STORE_S();
    __syncthreads();

    for (int kt = 0; kt < KT; kt++) {
        if (kt + 1 < KT) LOAD_G(kt + 1);

        #pragma unroll
        for (int ks = 0; ks < 4; ks++) {
            uint32_t af[4][4], bf[4][2];
            #pragma unroll
            for (int mt = 0; mt < 4; mt++) {
                const float* ap = As + (wm + mt * 16) * 36 + ks * 8;
                af[mt][0] = __float_as_uint(ap[g * 36 + t]);
                af[mt][1] = __float_as_uint(ap[(g + 8) * 36 + t]);
                af[mt][2] = __float_as_uint(ap[g * 36 + t + 4]);
                af[mt][3] = __float_as_uint(ap[(g + 8) * 36 + t + 4]);
            }
            #pragma unroll
            for (int nt = 0; nt < 4; nt++) {
                const float* bp = Bs + (ks * 8) * 136 + wn + nt * 8;
                bf[nt][0] = __float_as_uint(bp[t * 136 + g]);
                bf[nt][1] = __float_as_uint(bp[(t + 4) * 136 + g]);
            }
            #pragma unroll
            for (int mt = 0; mt < 4; mt++)
                #pragma unroll
                for (int nt = 0; nt < 4; nt++)
                    MMA_TF32(c[mt][nt], af[mt], bf[nt]);
        }

        __syncthreads();
        if (kt + 1 < KT) {
            STORE_S();
            __syncthreads();
        }
    }

    #pragma unroll
    for (int mt = 0; mt < 4; mt++) {
        #pragma unroll
        for (int nt = 0; nt < 4; nt++) {
            int row0 = bm + wm + mt * 16 + g;
            int col  = bn + wn + nt * 8 + 2 * t;
            float v0 = c[mt][nt][0], v1 = c[mt][nt][1];
            float v2 = c[mt][nt][2], v3 = c[mt][nt][3];
            if (EPI == 1) {
                float b0 = bias[col], b1 = bias[col + 1];
                v0 = fmaxf(v0 + b0, 0.f); v1 = fmaxf(v1 + b1, 0.f);
                v2 = fmaxf(v2 + b0, 0.f); v3 = fmaxf(v3 + b1, 0.f);
            }
            float2 p01 = make_float2(v0, v1);
            float2 p23 = make_float2(v2, v3);
            *(float2*)(C + (long)row0 * N + col)       = p01;
            *(float2*)(C + (long)(row0 + 8) * N + col) = p23;
        }
    }
    #undef LOAD_G
    #undef STORE_S
}

// ---------------------------------------------------------------------------
// MMA flash causal rel-attention, v2.
// grid (32 qtiles [longest first], 16 heads, 2 batch), 512 threads (16 warps).
// Sliding-window G: consecutive j-tiles share 64 of the 128 rel-pos columns,
// so each iter computes only the NEW 64 cols (double-buffered halves).
// Per iter:
//   warps 0-7 : S = (Q+rwb) K^T  (64x64x64)      [16x32 warp tiles]
//   warps 8-15: Gnew = (Q+rrb) Rnew^T (64x64x64) [16x32 warp tiles] (parallel!)
//   softmax on S[ti][tj] + G[ti][63-ti+tj] (16 warps x 4 rows)
//   O += P V (16 warps, 16x16 tiles)
// ---------------------------------------------------------------------------
#define ATT_STR 68     // 64+4 pad: frag-load banks (4g+t)%32 conflict-free
#define VS_STR  76     // 64+12 pad: PV B-frag banks (12t+g)%32 conflict-free

__global__ void __launch_bounds__(512, 1)
attn_mma_kernel(const float* __restrict__ rwb, const float* __restrict__ rrb)
{
    extern __shared__ float sm[];
    float* QW = sm;                      // 64*68  (q + r_w_bias, tf32)
    float* QR = QW + 64 * ATT_STR;       // 64*68  (q + r_r_bias, tf32)
    float* Ks = QR + 64 * ATT_STR;       // 64*68  K[tj][d]
    float* SP = Ks + 64 * ATT_STR;       // 64*68  S then P (in place)
    float* Rs = SP + 64 * ATT_STR;       // 64*68  new rel-pos rows
    float* G0 = Rs + 64 * ATT_STR;       // 64*68  G half buffer A
    float* G1 = G0 + 64 * ATT_STR;       // 64*68  G half buffer B
    float* Vs = G1 + 64 * ATT_STR;       // 64*76  V[tj][d]
    float* corr_s = Vs + 64 * VS_STR;    // 64
    float* linv_s = corr_s + 64;         // 64

    const int qt = 31 - (int)blockIdx.x; // longest q-tiles launch first
    const int n  = blockIdx.y;
    const int b  = blockIdx.z;
    const int i0 = qt * 64;
    const int tid = threadIdx.x;
    const int w = tid >> 5, l = tid & 31;
    const int g = l >> 2, t = l & 3;
    const float scale = 0.125f;

    // S/G mma layout (8-warp groups): 16x32 tiles
    const int sg_roff = ((w & 7) >> 1) * 16;
    const int sg_coff = (w & 1) * 32;
    // PV layout (16 warps): 16x16 tiles
    const int pv_roff = (w >> 2) * 16;
    const int pv_coff = (w & 3) * 16;

    // ---- load Q tile + biases (once) ----
    for (int f = tid; f < 64 * 16; f += 512) {
        int ti = f >> 4, d4 = (f & 15) * 4;
        float4 q  = *(const float4*)&g_heads[(size_t)((i0 + ti) * BSZ + b) * (3 * DM) + n * DH + d4];
        float4 wb = *(const float4*)&rwb[n * DH + d4];
        float4 rb = *(const float4*)&rrb[n * DH + d4];
        float4 qw4, qr4;
        qw4.x = to_tf32(q.x + wb.x); qw4.y = to_tf32(q.y + wb.y);
        qw4.z = to_tf32(q.z + wb.z); qw4.w = to_tf32(q.w + wb.w);
        qr4.x = to_tf32(q.x + rb.x); qr4.y = to_tf32(q.y + rb.y);
        qr4.z = to_tf32(q.z + rb.z); qr4.w = to_tf32(q.w + rb.w);
        *(float4*)(QW + ti * ATT_STR + d4) = qw4;
        *(float4*)(QR + ti * ATT_STR + d4) = qr4;
    }

    // ---- pre-loop: compute G low half of window jt=0 into G0 ----
    // window jt: cols ml <-> m = (QL-64-i0+j0) + ml ; low half ml in [0,64)
    {
        const int mmin0 = QL - 64 - i0;     // >= 0 always; m < QL always (low half)
        for (int f = tid; f < 64 * 16; f += 512) {
            int ml = f >> 4, d4 = (f & 15) * 4;
            float4 rv = *(const float4*)&g_rk[(size_t)(mmin0 + ml) * DM + n * DH + d4];
            float4 o;
            o.x = to_tf32(rv.x); o.y = to_tf32(rv.y);
            o.z = to_tf32(rv.z); o.w = to_tf32(rv.w);
            *(float4*)(Rs + ml * ATT_STR + d4) = o;
        }
        __syncthreads();
        // 16 warps, 16x16 tiles over the 64x64 Glow
        float gc[2][4];
        #pragma unroll
        for (int nt = 0; nt < 2; nt++)
            #pragma unroll
            for (int q = 0; q < 4; q++) gc[nt][q] = 0.f;
        #pragma unroll
        for (int ks = 0; ks < 8; ks++) {
            const int ko = ks * 8;
            const float* qa = QR + (pv_roff + g) * ATT_STR + ko + t;
            uint32_t ar[4] = { __float_as_uint(qa[0]),
                               __float_as_uint(qa[8 * ATT_STR]),
                               __float_as_uint(qa[4]),
                               __float_as_uint(qa[8 * ATT_STR + 4]) };
            #pragma unroll
            for (int nt = 0; nt < 2; nt++) {
                const float* rp = Rs + (pv_coff + nt * 8 + g) * ATT_STR + ko + t;
                uint32_t bf[2] = { __float_as_uint(rp[0]), __float_as_uint(rp[4]) };
                MMA_TF32(gc[nt], ar, bf);
            }
        }
        #pragma unroll
        for (int nt = 0; nt < 2; nt++) {
            float* p = G0 + (pv_roff + g) * ATT_STR + pv_coff + nt * 8 + 2 * t;
            p[0] = gc[nt][0] * scale; p[1] = gc[nt][1] * scale;
            p[8 * ATT_STR] = gc[nt][2] * scale; p[8 * ATT_STR + 1] = gc[nt][3] * scale;
        }
    }

    float* Glo = G0;
    float* Ghi = G1;

    float O[2][4];
    #pragma unroll
    for (int nt = 0; nt < 2; nt++)
        #pragma unroll
        for (int q = 0; q < 4; q++) O[nt][q] = 0.f;
    float mrow[4], lrow[4];
    #pragma unroll
    for (int s = 0; s < 4; s++) { mrow[s] = -INFINITY; lrow[s] = 0.f; }

    for (int jt = 0; jt <= qt; jt++) {
        const int j0 = jt * 64;
        __syncthreads();   // protect smem from previous iter's readers

        // ---- load K, V, Rs(new high half) ----
        for (int f = tid; f < 64 * 16; f += 512) {
            int tj = f >> 4, d4 = (f & 15) * 4;
            size_t base = (size_t)((j0 + tj) * BSZ + b) * (3 * DM) + n * DH + d4;
            float4 kv = *(const float4*)&g_heads[base + DM];
            float4 vv = *(const float4*)&g_heads[base + 2 * DM];
            float4 ko4, vo4;
            ko4.x = to_tf32(kv.x); ko4.y = to_tf32(kv.y);
            ko4.z = to_tf32(kv.z); ko4.w = to_tf32(kv.w);
            vo4.x = to_tf32(vv.x); vo4.y = to_tf32(vv.y);
            vo4.z = to_tf32(vv.z); vo4.w = to_tf32(vv.w);
            *(float4*)(Ks + tj * ATT_STR + d4) = ko4;
            *(float4*)(Vs + tj * VS_STR  + d4) = vo4;
        }
        const int mbase = QL - i0 + j0;   // high half: m = mbase + ml
        for (int f = tid; f < 64 * 16; f += 512) {
            int ml = f >> 4, d4 = (f & 15) * 4;
            int m = mbase + ml;
            float4 o = make_float4(0.f, 0.f, 0.f, 0.f);
            if (m < QL) {
                float4 rv = *(const float4*)&g_rk[(size_t)m * DM + n * DH + d4];
                o.x = to_tf32(rv.x); o.y = to_tf32(rv.y);
                o.z = to_tf32(rv.z); o.w = to_tf32(rv.w);
            }
            *(float4*)(Rs + ml * ATT_STR + d4) = o;
        }
        __syncthreads();

        // ---- concurrent mma: warps 0-7 do S, warps 8-15 do G(new half) ----
        {
            const float* Asrc = (w < 8) ? QW : QR;
            const float* Bsrc = (w < 8) ? Ks : Rs;
            float* Dst        = (w < 8) ? SP : Ghi;
            float acc[4][4];
            #pragma unroll
            for (int nt = 0; nt < 4; nt++)
                #pragma unroll
                for (int q = 0; q < 4; q++) acc[nt][q] = 0.f;
            #pragma unroll
            for (int ks = 0; ks < 8; ks++) {
                const int ko = ks * 8;
                const float* qa = Asrc + (sg_roff + g) * ATT_STR + ko + t;
                uint32_t af[4] = { __float_as_uint(qa[0]),
                                   __float_as_uint(qa[8 * ATT_STR]),
                                   __float_as_uint(qa[4]),
                                   __float_as_uint(qa[8 * ATT_STR + 4]) };
                #pragma unroll
                for (int nt = 0; nt < 4; nt++) {
                    const float* bp = Bsrc + (sg_coff + nt * 8 + g) * ATT_STR + ko + t;
                    uint32_t bf[2] = { __float_as_uint(bp[0]), __float_as_uint(bp[4]) };
                    MMA_TF32(acc[nt], af, bf);
                }
            }
            #pragma unroll
            for (int nt = 0; nt < 4; nt++) {
                float* p = Dst + (sg_roff + g) * ATT_STR + sg_coff + nt * 8 + 2 * t;
                p[0] = acc[nt][0] * scale; p[1] = acc[nt][1] * scale;
                p[8 * ATT_STR] = acc[nt][2] * scale; p[8 * ATT_STR + 1] = acc[nt][3] * scale;
            }
        }
        __syncthreads();

        // ---- online softmax: warp w rows 4w..4w+3, lane cols {l, l+32} ----
        const bool diag = (jt == qt);
        #pragma unroll
        for (int s = 0; s < 4; s++) {
            const int ti = w * 4 + s;
            const int ml0 = 63 - ti + l;
            const int ml1 = ml0 + 32;
            float gv0 = (ml0 < 64) ? Glo[ti * ATT_STR + ml0] : Ghi[ti * ATT_STR + ml0 - 64];
            float gv1 = (ml1 < 64) ? Glo[ti * ATT_STR + ml1] : Ghi[ti * ATT_STR + ml1 - 64];
            float s0 = SP[ti * ATT_STR + l]      + gv0;
            float s1 = SP[ti * ATT_STR + 32 + l] + gv1;
            if (diag) {
                if (l > ti)      s0 = -INFINITY;
                if (l + 32 > ti) s1 = -INFINITY;
            }
            float rm = fmaxf(s0, s1);
            #pragma unroll
            for (int off = 16; off; off >>= 1)
                rm = fmaxf(rm, __shfl_xor_sync(0xffffffffu, rm, off));
            float mnew = fmaxf(mrow[s], rm);
            float corr = __expf(mrow[s] - mnew);
            float p0 = __expf(s0 - mnew);
            float p1 = __expf(s1 - mnew);
            float rs = p0 + p1;
            #pragma unroll
            for (int off = 16; off; off >>= 1)
                rs += __shfl_xor_sync(0xffffffffu, rs, off);
            lrow[s] = lrow[s] * corr + rs;
            mrow[s] = mnew;
            SP[ti * ATT_STR + l]      = to_tf32(p0);
            SP[ti * ATT_STR + 32 + l] = to_tf32(p1);
            if (l == 0) corr_s[ti] = corr;
        }
        __syncthreads();

        // ---- O = O*corr + P @ V  (16 warps, 16x16 tiles) ----
        {
            float c0 = corr_s[pv_roff + g], c1 = corr_s[pv_roff + g + 8];
            #pragma unroll
            for (int nt = 0; nt < 2; nt++) {
                O[nt][0] *= c0; O[nt][1] *= c0;
                O[nt][2] *= c1; O[nt][3] *= c1;
            }
        }
        #pragma unroll
        for (int ks = 0; ks < 8; ks++) {
            const int ko = ks * 8;
            const float* pp = SP + (pv_roff + g) * ATT_STR + ko + t;
            uint32_t ap[4] = { __float_as_uint(pp[0]),
                               __float_as_uint(pp[8 * ATT_STR]),
                               __float_as_uint(pp[4]),
                               __float_as_uint(pp[8 * ATT_STR + 4]) };
            #pragma unroll
            for (int nt = 0; nt < 2; nt++) {
                const float* vp = Vs + (ko + t) * VS_STR + pv_coff + nt * 8 + g;
                uint32_t bf[2] = { __float_as_uint(vp[0]), __float_as_uint(vp[4 * VS_STR]) };
                MMA_TF32(O[nt], ap, bf);
            }
        }

        // slide the G window
        float* tmp = Glo; Glo = Ghi; Ghi = tmp;
    }

    // ---- final normalization + store ----
    #pragma unroll
    for (int s = 0; s < 4; s++)
        if (l == 0) linv_s[w * 4 + s] = 1.f / lrow[s];
    __syncthreads();

    #pragma unroll
    for (int nt = 0; nt < 2; nt++) {
        const int col = n * DH + pv_coff + nt * 8 + 2 * t;
        const int r0 = pv_roff + g, r1 = pv_roff + g + 8;
        const float li0 = linv_s[r0], li1 = linv_s[r1];
        size_t ro0 = (size_t)((i0 + r0) * BSZ + b) * DM;
        size_t ro1 = (size_t)((i0 + r1) * BSZ + b) * DM;
        float2 o0 = make_float2(O[nt][0] * li0, O[nt][1] * li0);
        float2 o1 = make_float2(O[nt][2] * li1, O[nt][3] * li1);
        *(float2*)&g_attnvec[ro0 + col] = o0;
        *(float2*)&g_attnvec[ro1 + col] = o1;
    }
}

// ---------------------------------------------------------------------------
// Residual add (+optional bias) + LayerNorm, one row (1024) per block.
// ---------------------------------------------------------------------------
__global__ void __launch_bounds__(256)
ln_kernel(const float* __restrict__ resid, const float* __restrict__ y,
          const float* __restrict__ bias, const float* __restrict__ gam,
          const float* __restrict__ bet, float* __restrict__ out)
{
    const int row = blockIdx.x;
    const int tid = threadIdx.x;
    __shared__ float buf[DM];
    __shared__ float red[8];

    float lsum = 0.f;
    for (int d = tid; d < DM; d += 256) {
        float v = resid[(long)row * DM + d] + y[(long)row * DM + d];
        if (bias) v += bias[d];
        buf[d] = v;
        lsum += v;
    }
    #pragma unroll
    for (int off = 16; off; off >>= 1) lsum += __shfl_xor_sync(0xffffffffu, lsum, off);
    if ((tid & 31) == 0) red[tid >> 5] = lsum;
    __syncthreads();
    float tot = 0.f;
    #pragma unroll
    for (int i = 0; i < 8; i++) tot += red[i];
    const float mean = tot * (1.f / DM);
    __syncthreads();

    float lv = 0.f;
    for (int d = tid; d < DM; d += 256) {
        float t = buf[d] - mean;
        lv += t * t;
    }
    #pragma unroll
    for (int off = 16; off; off >>= 1) lv += __shfl_xor_sync(0xffffffffu, lv, off);
    if ((tid & 31) == 0) red[tid >> 5] = lv;
    __syncthreads();
    float vtot = 0.f;
    #pragma unroll
    for (int i = 0; i < 8; i++) vtot += red[i];
    const float inv = rsqrtf(vtot * (1.f / DM) + 1e-5f);

    for (int d = tid; d < DM; d += 256)
        out[(long)row * DM + d] = (buf[d] - mean) * inv * gam[d] + bet[d];
}

// ---------------------------------------------------------------------------
// Host launch
// ---------------------------------------------------------------------------
extern "C" void kernel_launch(void* const* d_in, const int* in_sizes, int n_in,
                              void* d_out, int out_size)
{
    const float* w      = (const float*)d_in[0];
    const float* r      = (const float*)d_in[1];
    const float* rwb    = (const float*)d_in[2];
    const float* rrb    = (const float*)d_in[3];
    // d_in[4] = attn_mask (causal triu, implicit)
    const float* qkv_w  = (const float*)d_in[5];
    const float* rnet_w = (const float*)d_in[6];
    const float* o_w    = (const float*)d_in[7];
    const float* ln1_g  = (const float*)d_in[8];
    const float* ln1_b  = (const float*)d_in[9];
    const float* ffn_w1 = (const float*)d_in[10];
    const float* ffn_b1 = (const float*)d_in[11];
    const float* ffn_w2 = (const float*)d_in[12];
    const float* ffn_b2 = (const float*)d_in[13];
    const float* ln2_g  = (const float*)d_in[14];
    const float* ln2_b  = (const float*)d_in[15];

    float *heads, *rk, *attnvec, *attnout, *x, *h, *core;
    cudaGetSymbolAddress((void**)&heads,   g_heads);
    cudaGetSymbolAddress((void**)&rk,      g_rk);
    cudaGetSymbolAddress((void**)&attnvec, g_attnvec);
    cudaGetSymbolAddress((void**)&attnout, g_attnout);
    cudaGetSymbolAddress((void**)&x,       g_x);
    cudaGetSymbolAddress((void**)&h,       g_h);
    cudaGetSymbolAddress((void**)&core,    g_core);

    // 1) qkv projection: [4096,1024] @ [1024,3072]
    gemm_tf32<0><<<dim3(3 * DM / 128, NTOK / 128), 256>>>(w, qkv_w, heads, nullptr,
                                                          NTOK, 3 * DM, DM);
    // 2) r_k: [2048,1024] @ [1024,1024]
    gemm_tf32<0><<<dim3(DM / 128, QL / 128), 256>>>(r, rnet_w, rk, nullptr,
                                                    QL, DM, DM);
    // 3) attention (tf32 mma flash, sliding-G, 512 threads)
    {
        const int smem = (7 * 64 * ATT_STR + 64 * VS_STR + 128) * (int)sizeof(float);
        cudaFuncSetAttribute(attn_mma_kernel,
                             cudaFuncAttributeMaxDynamicSharedMemorySize, smem);
        attn_mma_kernel<<<dim3(QL / 64, NH, BSZ), 512, smem>>>(rwb, rrb);
    }
    // 4) o projection
    gemm_tf32<0><<<dim3(DM / 128, NTOK / 128), 256>>>(attnvec, o_w, attnout, nullptr,
                                                      NTOK, DM, DM);
    // 5) x = LN(w + attn_out)
    ln_kernel<<<NTOK, 256>>>(w, attnout, nullptr, ln1_g, ln1_b, x);
    // 6) h = relu(x @ ffn_w1 + b1)
    gemm_tf32<1><<<dim3(DI / 128, NTOK / 128), 256>>>(x, ffn_w1, h, ffn_b1,
                                                      NTOK, DI, DM);
    // 7) core = h @ ffn_w2  (bias b2 added in LN)
    gemm_tf32<0><<<dim3(DM / 128, NTOK / 128), 256>>>(h, ffn_w2, core, nullptr,
                                                      NTOK, DM, DI);
    // 8) out = LN(x + core + b2)
    ln_kernel<<<NTOK, 256>>>(x, core, ffn_b2, ln2_g, ln2_b, (float*)d_out);
}

// round 6
// speedup vs baseline: 1.4033x; 1.4033x over previous
#include <cuda_runtime.h>
#include <cuda_bf16.h>
#include <math.h>
#include <stdint.h>

// ---------------------------------------------------------------------------
// Problem constants
// ---------------------------------------------------------------------------
#define QL 2048
#define BSZ 2
#define DM 1024
#define NH 16
#define DH 64
#define DI 4096
#define NTOK (QL*BSZ)          // 4096 rows, row t = i*BSZ + b

// ---------------------------------------------------------------------------
// Scratch (device globals; no allocation allowed)
// ---------------------------------------------------------------------------
__device__ float g_heads[NTOK * 3 * DM];   // qkv projections  [4096, 3072]
__device__ float g_rk[QL * DM];            // r @ r_net_w      [2048, 1024]
__device__ float g_attnvec[NTOK * DM];     // attention output [4096, 1024]
__device__ float g_attnout[NTOK * DM];     // o-proj output
__device__ float g_x[NTOK * DM];           // after LN1
__device__ float g_h[NTOK * DI];           // ffn hidden       [4096, 4096]
__device__ float g_core[NTOK * DM];        // ffn output

// ---------------------------------------------------------------------------
// tf32 helpers
// ---------------------------------------------------------------------------
__device__ __forceinline__ float to_tf32(float v) {
    uint32_t u;
    asm("cvt.rna.tf32.f32 %0, %1;" : "=r"(u) : "f"(v));
    return __uint_as_float(u);
}

#define MMA_TF32(d, a, b)                                                      \
    asm volatile(                                                              \
        "mma.sync.aligned.m16n8k8.row.col.f32.tf32.tf32.f32 "                  \
        "{%0,%1,%2,%3},{%4,%5,%6,%7},{%8,%9},{%0,%1,%2,%3};\n"                 \
        : "+f"(d[0]), "+f"(d[1]), "+f"(d[2]), "+f"(d[3])                       \
        : "r"(a[0]), "r"(a[1]), "r"(a[2]), "r"(a[3]), "r"(b[0]), "r"(b[1]))

// ---------------------------------------------------------------------------
// Generic tf32 GEMM: C[M,N] = A[M,K] @ B[K,N]  (+bias)(+relu per EPI)
// Tile 128x128x32, 256 threads (8 warps: 2 (m) x 4 (n), warp tile 64x32).
// EPI: 0 = plain store, 1 = bias + relu
// ---------------------------------------------------------------------------
template <int EPI>
__global__ void __launch_bounds__(256)
gemm_tf32(const float* __restrict__ A, const float* __restrict__ B,
          float* __restrict__ C, const float* __restrict__ bias,
          int M, int N, int K)
{
    const int bm = blockIdx.y * 128;
    const int bn = blockIdx.x * 128;

    __shared__ float As[128 * 36];   // stride 36 (pad)
    __shared__ float Bs[32 * 136];   // stride 136 (pad -> conflict-free frags)

    const int tid = threadIdx.x;
    const int w   = tid >> 5;
    const int l   = tid & 31;
    const int g   = l >> 2;   // group id 0..7
    const int t   = l & 3;    // thread-in-group 0..3
    const int wm  = (w & 1) * 64;
    const int wn  = (w >> 1) * 32;

    float c[4][4][4];
    #pragma unroll
    for (int mt = 0; mt < 4; mt++)
        #pragma unroll
        for (int nt = 0; nt < 4; nt++)
            #pragma unroll
            for (int q = 0; q < 4; q++) c[mt][nt][q] = 0.f;

    float4 ra[4], rb[4];

    const int KT = K / 32;

    #define LOAD_G(kt)                                                         \
        {                                                                      \
            const float* Ap = A + (long)bm * K + (kt) * 32;                    \
            _Pragma("unroll")                                                  \
            for (int it = 0; it < 4; it++) {                                   \
                int f = tid + it * 256;                                        \
                int rr = f >> 3, c4 = f & 7;                                   \
                ra[it] = *(const float4*)(Ap + (long)rr * K + c4 * 4);         \
            }                                                                  \
            const float* Bp = B + (long)(kt) * 32 * N + bn;                    \
            _Pragma("unroll")                                                  \
            for (int it = 0; it < 4; it++) {                                   \
                int f = tid + it * 256;                                        \
                int rr = f >> 5, c4 = f & 31;                                  \
                rb[it] = *(const float4*)(Bp + (long)rr * N + c4 * 4);         \
            }                                                                  \
        }

    #define STORE_S()                                                          \
        {                                                                      \
            _Pragma("unroll")                                                  \
            for (int it = 0; it < 4; it++) {                                   \
                int f = tid + it * 256;                                        \
                int rr = f >> 3, c4 = f & 7;                                   \
                float* p = As + rr * 36 + c4 * 4;                              \
                p[0] = to_tf32(ra[it].x); p[1] = to_tf32(ra[it].y);            \
                p[2] = to_tf32(ra[it].z); p[3] = to_tf32(ra[it].w);            \
            }                                                                  \
            _Pragma("unroll")                                                  \
            for (int it = 0; it < 4; it++) {                                   \
                int f = tid + it * 256;                                        \
                int rr = f >> 5, c4 = f & 31;                                  \
                float* p = Bs + rr * 136 + c4 * 4;                             \
                p[0] = to_tf32(rb[it].x); p[1] = to_tf32(rb[it].y);            \
                p[2] = to_tf32(rb[it].z); p[3] = to_tf32(rb[it].w);            \
            }                                                                  \
        }

    LOAD_G(0);
    STORE_S();
    __syncthreads();

    for (int kt = 0; kt < KT; kt++) {
        if (kt + 1 < KT) LOAD_G(kt + 1);

        #pragma unroll
        for (int ks = 0; ks < 4; ks++) {
            uint32_t af[4][4], bf[4][2];
            #pragma unroll
            for (int mt = 0; mt < 4; mt++) {
                const float* ap = As + (wm + mt * 16) * 36 + ks * 8;
                af[mt][0] = __float_as_uint(ap[g * 36 + t]);
                af[mt][1] = __float_as_uint(ap[(g + 8) * 36 + t]);
                af[mt][2] = __float_as_uint(ap[g * 36 + t + 4]);
                af[mt][3] = __float_as_uint(ap[(g + 8) * 36 + t + 4]);
            }
            #pragma unroll
            for (int nt = 0; nt < 4; nt++) {
                const float* bp = Bs + (ks * 8) * 136 + wn + nt * 8;
                bf[nt][0] = __float_as_uint(bp[t * 136 + g]);
                bf[nt][1] = __float_as_uint(bp[(t + 4) * 136 + g]);
            }
            #pragma unroll
            for (int mt = 0; mt < 4; mt++)
                #pragma unroll
                for (int nt = 0; nt < 4; nt++)
                    MMA_TF32(c[mt][nt], af[mt], bf[nt]);
        }

        __syncthreads();
        if (kt + 1 < KT) {
            STORE_S();
            __syncthreads();
        }
    }

    #pragma unroll
    for (int mt = 0; mt < 4; mt++) {
        #pragma unroll
        for (int nt = 0; nt < 4; nt++) {
            int row0 = bm + wm + mt * 16 + g;
            int col  = bn + wn + nt * 8 + 2 * t;
            float v0 = c[mt][nt][0], v1 = c[mt][nt][1];
            float v2 = c[mt][nt][2], v3 = c[mt][nt][3];
            if (EPI == 1) {
                float b0 = bias[col], b1 = bias[col + 1];
                v0 = fmaxf(v0 + b0, 0.f); v1 = fmaxf(v1 + b1, 0.f);
                v2 = fmaxf(v2 + b0, 0.f); v3 = fmaxf(v3 + b1, 0.f);
            }
            float2 p01 = make_float2(v0, v1);
            float2 p23 = make_float2(v2, v3);
            *(float2*)(C + (long)row0 * N + col)       = p01;
            *(float2*)(C + (long)(row0 + 8) * N + col) = p23;
        }
    }
    #undef LOAD_G
    #undef STORE_S
}

// ---------------------------------------------------------------------------
// MMA flash causal rel-attention, v3 (2 CTAs/SM).
// grid (32 qtiles [longest first], 16 heads, 2 batch), 256 threads (8 warps).
// smem 105 KB -> 2 resident CTAs overlap the barrier-separated phases.
//  - Q stored raw once; r_w/r_r biases added per-fragment in registers.
//  - Sliding-window G: only the new 64 rel-pos columns per iter
//    (double-buffered G halves), rel-pos B-fragments loaded from global.
// Per iter (warp tile 16x32 at (roff, coff)):
//   S = (Q+rwb) K^T      32 mma/warp
//   Gnew = (Q+rrb) Rnew^T 32 mma/warp  (B frags from g_rk, L1-cached)
//   online softmax on S[ti][tj] + G[ti][63-ti+tj]  (8 rows/warp)
//   O += P V             32 mma/warp
// ---------------------------------------------------------------------------
#define ATT_STR 68     // 64+4 pad: frag-load banks (4g+t)%32 conflict-free
#define VS_STR  76     // 64+12 pad: PV B-frag banks (12t+g)%32 conflict-free

__global__ void __launch_bounds__(256, 2)
attn_mma_kernel(const float* __restrict__ rwb, const float* __restrict__ rrb)
{
    extern __shared__ float sm[];
    float* Qs = sm;                      // 64*68 raw fp32 q
    float* Ks = Qs + 64 * ATT_STR;       // 64*68 K[tj][d] (tf32)
    float* SP = Ks + 64 * ATT_STR;       // 64*68 S then P (in place)
    float* G0 = SP + 64 * ATT_STR;       // 64*68 G half buffer A
    float* G1 = G0 + 64 * ATT_STR;       // 64*68 G half buffer B
    float* Vs = G1 + 64 * ATT_STR;       // 64*76 V[tj][d] (tf32)
    float* bwS = Vs + 64 * VS_STR;       // 64  r_w_bias head slice
    float* brS = bwS + 64;               // 64  r_r_bias head slice
    float* corr_s = brS + 64;            // 64
    float* linv_s = corr_s + 64;         // 64

    const int qt = 31 - (int)blockIdx.x; // longest q-tiles launch first
    const int n  = blockIdx.y;
    const int b  = blockIdx.z;
    const int i0 = qt * 64;
    const int tid = threadIdx.x;
    const int w = tid >> 5, l = tid & 31;
    const int g = l >> 2, t = l & 3;
    const int roff = (w >> 1) * 16;      // mma row offset
    const int coff = (w & 1) * 32;       // mma col offset
    const float scale = 0.125f;

    // ---- prologue: biases + raw Q tile ----
    if (tid < 64) {
        bwS[tid] = rwb[n * DH + tid];
        brS[tid] = rrb[n * DH + tid];
    }
    for (int f = tid; f < 64 * 16; f += 256) {
        int ti = f >> 4, d4 = (f & 15) * 4;
        float4 q = *(const float4*)&g_heads[(size_t)((i0 + ti) * BSZ + b) * (3 * DM) + n * DH + d4];
        *(float4*)(Qs + ti * ATT_STR + d4) = q;
    }
    __syncthreads();

    const float* rk_head = g_rk + n * DH;

    // ---- pre-loop: G low half of window jt=0 into G0 ----
    {
        const int mmin0 = QL - 64 - i0;   // rows always in [0, QL)
        float gc[4][4];
        #pragma unroll
        for (int nt = 0; nt < 4; nt++)
            #pragma unroll
            for (int q = 0; q < 4; q++) gc[nt][q] = 0.f;
        const float* gp[4];
        #pragma unroll
        for (int nt = 0; nt < 4; nt++)
            gp[nt] = rk_head + (size_t)(mmin0 + coff + nt * 8 + g) * DM + t;
        #pragma unroll
        for (int ks = 0; ks < 8; ks++) {
            const int ko = ks * 8;
            const float* qa = Qs + (roff + g) * ATT_STR + ko + t;
            float br0 = brS[ko + t], br4 = brS[ko + t + 4];
            uint32_t ar[4] = {
                __float_as_uint(to_tf32(qa[0] + br0)),
                __float_as_uint(to_tf32(qa[8 * ATT_STR] + br0)),
                __float_as_uint(to_tf32(qa[4] + br4)),
                __float_as_uint(to_tf32(qa[8 * ATT_STR + 4] + br4)) };
            #pragma unroll
            for (int nt = 0; nt < 4; nt++) {
                uint32_t bf[2] = {
                    __float_as_uint(to_tf32(gp[nt][ko])),
                    __float_as_uint(to_tf32(gp[nt][ko + 4])) };
                MMA_TF32(gc[nt], ar, bf);
            }
        }
        #pragma unroll
        for (int nt = 0; nt < 4; nt++) {
            float* p = G0 + (roff + g) * ATT_STR + coff + nt * 8 + 2 * t;
            p[0] = gc[nt][0] * scale; p[1] = gc[nt][1] * scale;
            p[8 * ATT_STR] = gc[nt][2] * scale; p[8 * ATT_STR + 1] = gc[nt][3] * scale;
        }
    }

    float* Glo = G0;
    float* Ghi = G1;

    float O[4][4];
    #pragma unroll
    for (int nt = 0; nt < 4; nt++)
        #pragma unroll
        for (int q = 0; q < 4; q++) O[nt][q] = 0.f;
    float mrow[8], lrow[8];
    #pragma unroll
    for (int s = 0; s < 8; s++) { mrow[s] = -INFINITY; lrow[s] = 0.f; }

    for (int jt = 0; jt <= qt; jt++) {
        const int j0 = jt * 64;
        __syncthreads();   // previous iter's PV readers done with Ks/Vs/SP

        // ---- fill K, V (tf32) ----
        for (int f = tid; f < 64 * 16; f += 256) {
            int tj = f >> 4, d4 = (f & 15) * 4;
            size_t base = (size_t)((j0 + tj) * BSZ + b) * (3 * DM) + n * DH + d4;
            float4 kv = *(const float4*)&g_heads[base + DM];
            float4 vv = *(const float4*)&g_heads[base + 2 * DM];
            float4 ko4, vo4;
            ko4.x = to_tf32(kv.x); ko4.y = to_tf32(kv.y);
            ko4.z = to_tf32(kv.z); ko4.w = to_tf32(kv.w);
            vo4.x = to_tf32(vv.x); vo4.y = to_tf32(vv.y);
            vo4.z = to_tf32(vv.z); vo4.w = to_tf32(vv.w);
            *(float4*)(Ks + tj * ATT_STR + d4) = ko4;
            *(float4*)(Vs + tj * VS_STR  + d4) = vo4;
        }
        __syncthreads();

        // ---- S + Gnew mma (per warp: 16x32 of each) ----
        {
            const int mbase = QL - i0 + j0;   // high half: m = mbase + ml'
            float sc[4][4], gc[4][4];
            #pragma unroll
            for (int nt = 0; nt < 4; nt++)
                #pragma unroll
                for (int q = 0; q < 4; q++) { sc[nt][q] = 0.f; gc[nt][q] = 0.f; }

            const float* gp[4];
            bool valid[4];
            #pragma unroll
            for (int nt = 0; nt < 4; nt++) {
                int rowm = mbase + coff + nt * 8 + g;
                valid[nt] = (rowm < QL);
                gp[nt] = rk_head + (size_t)rowm * DM + t;
            }

            #pragma unroll
            for (int ks = 0; ks < 8; ks++) {
                const int ko = ks * 8;
                const float* qa = Qs + (roff + g) * ATT_STR + ko + t;
                float q0 = qa[0], q1 = qa[8 * ATT_STR];
                float q2 = qa[4], q3 = qa[8 * ATT_STR + 4];
                float bw0 = bwS[ko + t], bw4 = bwS[ko + t + 4];
                float br0 = brS[ko + t], br4 = brS[ko + t + 4];
                uint32_t aw[4] = {
                    __float_as_uint(to_tf32(q0 + bw0)),
                    __float_as_uint(to_tf32(q1 + bw0)),
                    __float_as_uint(to_tf32(q2 + bw4)),
                    __float_as_uint(to_tf32(q3 + bw4)) };
                uint32_t ar[4] = {
                    __float_as_uint(to_tf32(q0 + br0)),
                    __float_as_uint(to_tf32(q1 + br0)),
                    __float_as_uint(to_tf32(q2 + br4)),
                    __float_as_uint(to_tf32(q3 + br4)) };
                #pragma unroll
                for (int nt = 0; nt < 4; nt++) {
                    const float* kp = Ks + (coff + nt * 8 + g) * ATT_STR + ko + t;
                    uint32_t bfk[2] = { __float_as_uint(kp[0]), __float_as_uint(kp[4]) };
                    MMA_TF32(sc[nt], aw, bfk);
                    uint32_t bfr[2];
                    if (valid[nt]) {
                        bfr[0] = __float_as_uint(to_tf32(gp[nt][ko]));
                        bfr[1] = __float_as_uint(to_tf32(gp[nt][ko + 4]));
                    } else {
                        bfr[0] = 0u; bfr[1] = 0u;
                    }
                    MMA_TF32(gc[nt], ar, bfr);
                }
            }
            #pragma unroll
            for (int nt = 0; nt < 4; nt++) {
                float* ps = SP  + (roff + g) * ATT_STR + coff + nt * 8 + 2 * t;
                ps[0] = sc[nt][0] * scale; ps[1] = sc[nt][1] * scale;
                ps[8 * ATT_STR] = sc[nt][2] * scale; ps[8 * ATT_STR + 1] = sc[nt][3] * scale;
                float* pg = Ghi + (roff + g) * ATT_STR + coff + nt * 8 + 2 * t;
                pg[0] = gc[nt][0] * scale; pg[1] = gc[nt][1] * scale;
                pg[8 * ATT_STR] = gc[nt][2] * scale; pg[8 * ATT_STR + 1] = gc[nt][3] * scale;
            }
        }
        __syncthreads();

        // ---- online softmax: warp w rows 8w..8w+7, lane cols {l, l+32} ----
        const bool diag = (jt == qt);
        #pragma unroll
        for (int s = 0; s < 8; s++) {
            const int ti = w * 8 + s;
            const int ml0 = 63 - ti + l;
            const int ml1 = ml0 + 32;
            float gv0 = (ml0 < 64) ? Glo[ti * ATT_STR + ml0] : Ghi[ti * ATT_STR + ml0 - 64];
            float gv1 = (ml1 < 64) ? Glo[ti * ATT_STR + ml1] : Ghi[ti * ATT_STR + ml1 - 64];
            float s0 = SP[ti * ATT_STR + l]      + gv0;
            float s1 = SP[ti * ATT_STR + 32 + l] + gv1;
            if (diag) {
                if (l > ti)      s0 = -INFINITY;
                if (l + 32 > ti) s1 = -INFINITY;
            }
            float rm = fmaxf(s0, s1);
            #pragma unroll
            for (int off = 16; off; off >>= 1)
                rm = fmaxf(rm, __shfl_xor_sync(0xffffffffu, rm, off));
            float mnew = fmaxf(mrow[s], rm);
            float corr = __expf(mrow[s] - mnew);
            float p0 = __expf(s0 - mnew);
            float p1 = __expf(s1 - mnew);
            float rs = p0 + p1;
            #pragma unroll
            for (int off = 16; off; off >>= 1)
                rs += __shfl_xor_sync(0xffffffffu, rs, off);
            lrow[s] = lrow[s] * corr + rs;
            mrow[s] = mnew;
            SP[ti * ATT_STR + l]      = to_tf32(p0);
            SP[ti * ATT_STR + 32 + l] = to_tf32(p1);
            if (l == 0) corr_s[ti] = corr;
        }
        __syncthreads();

        // ---- O = O*corr + P @ V ----
        {
            float c0 = corr_s[roff + g], c1 = corr_s[roff + g + 8];
            #pragma unroll
            for (int nt = 0; nt < 4; nt++) {
                O[nt][0] *= c0; O[nt][1] *= c0;
                O[nt][2] *= c1; O[nt][3] *= c1;
            }
        }
        #pragma unroll
        for (int ks = 0; ks < 8; ks++) {
            const int ko = ks * 8;
            const float* pp = SP + (roff + g) * ATT_STR + ko + t;
            uint32_t ap[4] = { __float_as_uint(pp[0]),
                               __float_as_uint(pp[8 * ATT_STR]),
                               __float_as_uint(pp[4]),
                               __float_as_uint(pp[8 * ATT_STR + 4]) };
            #pragma unroll
            for (int nt = 0; nt < 4; nt++) {
                const float* vp = Vs + (ko + t) * VS_STR + coff + nt * 8 + g;
                uint32_t bf[2] = { __float_as_uint(vp[0]), __float_as_uint(vp[4 * VS_STR]) };
                MMA_TF32(O[nt], ap, bf);
            }
        }

        // slide the G window
        float* tmp = Glo; Glo = Ghi; Ghi = tmp;
    }

    // ---- final normalization + store ----
    #pragma unroll
    for (int s = 0; s < 8; s++)
        if (l == 0) linv_s[w * 8 + s] = 1.f / lrow[s];
    __syncthreads();

    #pragma unroll
    for (int nt = 0; nt < 4; nt++) {
        const int col = n * DH + coff + nt * 8 + 2 * t;
        const int r0 = roff + g, r1 = roff + g + 8;
        const float li0 = linv_s[r0], li1 = linv_s[r1];
        size_t ro0 = (size_t)((i0 + r0) * BSZ + b) * DM;
        size_t ro1 = (size_t)((i0 + r1) * BSZ + b) * DM;
        float2 o0 = make_float2(O[nt][0] * li0, O[nt][1] * li0);
        float2 o1 = make_float2(O[nt][2] * li1, O[nt][3] * li1);
        *(float2*)&g_attnvec[ro0 + col] = o0;
        *(float2*)&g_attnvec[ro1 + col] = o1;
    }
}

// ---------------------------------------------------------------------------
// Residual add (+optional bias) + LayerNorm, one row (1024) per block.
// ---------------------------------------------------------------------------
__global__ void __launch_bounds__(256)
ln_kernel(const float* __restrict__ resid, const float* __restrict__ y,
          const float* __restrict__ bias, const float* __restrict__ gam,
          const float* __restrict__ bet, float* __restrict__ out)
{
    const int row = blockIdx.x;
    const int tid = threadIdx.x;
    __shared__ float buf[DM];
    __shared__ float red[8];

    float lsum = 0.f;
    for (int d = tid; d < DM; d += 256) {
        float v = resid[(long)row * DM + d] + y[(long)row * DM + d];
        if (bias) v += bias[d];
        buf[d] = v;
        lsum += v;
    }
    #pragma unroll
    for (int off = 16; off; off >>= 1) lsum += __shfl_xor_sync(0xffffffffu, lsum, off);
    if ((tid & 31) == 0) red[tid >> 5] = lsum;
    __syncthreads();
    float tot = 0.f;
    #pragma unroll
    for (int i = 0; i < 8; i++) tot += red[i];
    const float mean = tot * (1.f / DM);
    __syncthreads();

    float lv = 0.f;
    for (int d = tid; d < DM; d += 256) {
        float t = buf[d] - mean;
        lv += t * t;
    }
    #pragma unroll
    for (int off = 16; off; off >>= 1) lv += __shfl_xor_sync(0xffffffffu, lv, off);
    if ((tid & 31) == 0) red[tid >> 5] = lv;
    __syncthreads();
    float vtot = 0.f;
    #pragma unroll
    for (int i = 0; i < 8; i++) vtot += red[i];
    const float inv = rsqrtf(vtot * (1.f / DM) + 1e-5f);

    for (int d = tid; d < DM; d += 256)
        out[(long)row * DM + d] = (buf[d] - mean) * inv * gam[d] + bet[d];
}

// ---------------------------------------------------------------------------
// Host launch
// ---------------------------------------------------------------------------
extern "C" void kernel_launch(void* const* d_in, const int* in_sizes, int n_in,
                              void* d_out, int out_size)
{
    const float* w      = (const float*)d_in[0];
    const float* r      = (const float*)d_in[1];
    const float* rwb    = (const float*)d_in[2];
    const float* rrb    = (const float*)d_in[3];
    // d_in[4] = attn_mask (causal triu, implicit)
    const float* qkv_w  = (const float*)d_in[5];
    const float* rnet_w = (const float*)d_in[6];
    const float* o_w    = (const float*)d_in[7];
    const float* ln1_g  = (const float*)d_in[8];
    const float* ln1_b  = (const float*)d_in[9];
    const float* ffn_w1 = (const float*)d_in[10];
    const float* ffn_b1 = (const float*)d_in[11];
    const float* ffn_w2 = (const float*)d_in[12];
    const float* ffn_b2 = (const float*)d_in[13];
    const float* ln2_g  = (const float*)d_in[14];
    const float* ln2_b  = (const float*)d_in[15];

    float *heads, *rk, *attnvec, *attnout, *x, *h, *core;
    cudaGetSymbolAddress((void**)&heads,   g_heads);
    cudaGetSymbolAddress((void**)&rk,      g_rk);
    cudaGetSymbolAddress((void**)&attnvec, g_attnvec);
    cudaGetSymbolAddress((void**)&attnout, g_attnout);
    cudaGetSymbolAddress((void**)&x,       g_x);
    cudaGetSymbolAddress((void**)&h,       g_h);
    cudaGetSymbolAddress((void**)&core,    g_core);

    // 1) qkv projection: [4096,1024] @ [1024,3072]
    gemm_tf32<0><<<dim3(3 * DM / 128, NTOK / 128), 256>>>(w, qkv_w, heads, nullptr,
                                                          NTOK, 3 * DM, DM);
    // 2) r_k: [2048,1024] @ [1024,1024]
    gemm_tf32<0><<<dim3(DM / 128, QL / 128), 256>>>(r, rnet_w, rk, nullptr,
                                                    QL, DM, DM);
    // 3) attention (tf32 mma flash, sliding-G, 105KB smem -> 2 CTAs/SM)
    {
        const int smem = (5 * 64 * ATT_STR + 64 * VS_STR + 4 * 64) * (int)sizeof(float);
        cudaFuncSetAttribute(attn_mma_kernel,
                             cudaFuncAttributeMaxDynamicSharedMemorySize, smem);
        attn_mma_kernel<<<dim3(QL / 64, NH, BSZ), 256, smem>>>(rwb, rrb);
    }
    // 4) o projection
    gemm_tf32<0><<<dim3(DM / 128, NTOK / 128), 256>>>(attnvec, o_w, attnout, nullptr,
                                                      NTOK, DM, DM);
    // 5) x = LN(w + attn_out)
    ln_kernel<<<NTOK, 256>>>(w, attnout, nullptr, ln1_g, ln1_b, x);
    // 6) h = relu(x @ ffn_w1 + b1)
    gemm_tf32<1><<<dim3(DI / 128, NTOK / 128), 256>>>(x, ffn_w1, h, ffn_b1,
                                                      NTOK, DI, DM);
    // 7) core = h @ ffn_w2  (bias b2 added in LN)
    gemm_tf32<0><<<dim3(DM / 128, NTOK / 128), 256>>>(h, ffn_w2, core, nullptr,
                                                      NTOK, DM, DI);
    // 8) out = LN(x + core + b2)
    ln_kernel<<<NTOK, 256>>>(x, core, ffn_b2, ln2_g, ln2_b, (float*)d_out);
}